// round 10
// baseline (speedup 1.0000x reference)
#include <cuda_runtime.h>
#include <math.h>

#define BSZ 8
#define LSEQ 512
#define DM 256
#define NH 8
#define DH 32
#define DS 30

#define TQ 8       // q rows per CTA (warp = head)
#define TK 32
#define NKT (LSEQ / TK)
#define NTHREADS 256

#define ST_K 36               // per-k stride (s padded 30->36, pads zero)
#define ST_Q (32 * ST_K + 4)  // 1156: +4 pad de-conflicts accumulate banks
#define P_STR 33

// ---- attn dynamic smem layout (float offsets) ----
#define OFF_QS 0                 // [8h][8q][32] = 2048
#define OFF_QW 2048              // [8h][8q][32] = 2048 (qwsk padded 30->32 zeros)
#define OFF_P  4096              // [64][33]     = 2112 (p tiles; wsk temp; ps in epilogue)
#define OFF_ST 6208              // [8q] * 1156  = 9248
#define SMEM_FLOATS (6208 + 9248)
#define SMEM_BYTES (SMEM_FLOATS * 4)

// scratch: qh, kh, vh, ctx, ktr (1M fl each) + scores0 (2M fl)
__device__ float g_scratch[5 * BSZ * LSEQ * DM + BSZ * LSEQ * LSEQ];
__device__ int g_mask_is_byte;

// ---------------------------------------------------------------------------
__global__ void detect_mask_kernel(const unsigned char* __restrict__ m, int nbytes)
{
    __shared__ int any;
    if (threadIdx.x == 0) any = 0;
    __syncthreads();
    int local = 0;
    for (int i = threadIdx.x; i < nbytes; i += blockDim.x)
        if ((i & 3) != 0 && m[i] != 0) local = 1;
    if (local) atomicOr(&any, 1);
    __syncthreads();
    if (threadIdx.x == 0) g_mask_is_byte = any;
}

// ---------------------------------------------------------------------------
// K transpose: ktr[b][n][m] = kh[b*512+m][n]
// ---------------------------------------------------------------------------
__global__ void __launch_bounds__(256) transpose_k(
    const float* __restrict__ kh, float* __restrict__ ktr)
{
    __shared__ float t[32][33];
    const int b = blockIdx.z;
    const int m0 = blockIdx.x * 32, n0 = blockIdx.y * 32;
    const int tx = threadIdx.x, ty = threadIdx.y;

    for (int r = ty; r < 32; r += 8)
        t[r][tx] = kh[(size_t)(b * LSEQ + m0 + r) * DM + n0 + tx];
    __syncthreads();
    for (int r = ty; r < 32; r += 8)
        ktr[(size_t)b * DM * LSEQ + (size_t)(n0 + r) * LSEQ + m0 + tx] = t[tx][r];
}

// ---------------------------------------------------------------------------
// SGEMM 128x128 tile, 256 threads, 8x8 microtile, double-buffered.
// ---------------------------------------------------------------------------
__device__ __forceinline__ void gemm128_body(
    const float* __restrict__ A, const float* __restrict__ W,
    const float* __restrict__ bias, float* __restrict__ C, float scale,
    int m0, int n0)
{
    __shared__ float As[2][8][128];
    __shared__ float Bs[2][8][128];

    const int tid = threadIdx.x;
    const int am = tid >> 1;
    const int ak = (tid & 1) * 4;
    const int br = tid >> 5;
    const int bc = (tid & 31) * 4;
    const int tx = tid & 15, ty = tid >> 4;

    float4 av = *reinterpret_cast<const float4*>(&A[(size_t)(m0 + am) * 256 + ak]);
    float4 bv = *reinterpret_cast<const float4*>(&W[(size_t)br * 256 + n0 + bc]);

    As[0][ak + 0][am] = av.x; As[0][ak + 1][am] = av.y;
    As[0][ak + 2][am] = av.z; As[0][ak + 3][am] = av.w;
    *reinterpret_cast<float4*>(&Bs[0][br][bc]) = bv;
    __syncthreads();

    float acc[8][8] = {};
    int buf = 0;

    for (int k0 = 0; k0 < 256; k0 += 8) {
        const bool more = (k0 + 8 < 256);
        if (more) {
            av = *reinterpret_cast<const float4*>(&A[(size_t)(m0 + am) * 256 + k0 + 8 + ak]);
            bv = *reinterpret_cast<const float4*>(&W[(size_t)(k0 + 8 + br) * 256 + n0 + bc]);
        }
#pragma unroll
        for (int kk = 0; kk < 8; kk++) {
            float a[8], b[8];
            *reinterpret_cast<float4*>(&a[0]) = *reinterpret_cast<const float4*>(&As[buf][kk][ty * 8]);
            *reinterpret_cast<float4*>(&a[4]) = *reinterpret_cast<const float4*>(&As[buf][kk][ty * 8 + 4]);
            *reinterpret_cast<float4*>(&b[0]) = *reinterpret_cast<const float4*>(&Bs[buf][kk][tx * 8]);
            *reinterpret_cast<float4*>(&b[4]) = *reinterpret_cast<const float4*>(&Bs[buf][kk][tx * 8 + 4]);
#pragma unroll
            for (int i = 0; i < 8; i++)
#pragma unroll
                for (int j = 0; j < 8; j++) acc[i][j] += a[i] * b[j];
        }
        if (more) {
            buf ^= 1;
            As[buf][ak + 0][am] = av.x; As[buf][ak + 1][am] = av.y;
            As[buf][ak + 2][am] = av.z; As[buf][ak + 3][am] = av.w;
            *reinterpret_cast<float4*>(&Bs[buf][br][bc]) = bv;
            __syncthreads();
        }
    }

    float bb[8];
#pragma unroll
    for (int j = 0; j < 8; j++) bb[j] = bias[n0 + tx * 8 + j];
#pragma unroll
    for (int i = 0; i < 8; i++) {
        float4 c0, c1;
        c0.x = (acc[i][0] + bb[0]) * scale; c0.y = (acc[i][1] + bb[1]) * scale;
        c0.z = (acc[i][2] + bb[2]) * scale; c0.w = (acc[i][3] + bb[3]) * scale;
        c1.x = (acc[i][4] + bb[4]) * scale; c1.y = (acc[i][5] + bb[5]) * scale;
        c1.z = (acc[i][6] + bb[6]) * scale; c1.w = (acc[i][7] + bb[7]) * scale;
        float* cp = &C[(size_t)(m0 + ty * 8 + i) * 256 + n0 + tx * 8];
        reinterpret_cast<float4*>(cp)[0] = c0;
        reinterpret_cast<float4*>(cp)[1] = c1;
    }
}

__global__ void __launch_bounds__(256) gemm128(
    const float* __restrict__ A, const float* __restrict__ W,
    const float* __restrict__ bias, float* __restrict__ C, float scale)
{
    gemm128_body(A, W, bias, C, scale, blockIdx.y * 128, blockIdx.x * 128);
}

__global__ void __launch_bounds__(256) qkv_gemm(
    const float* __restrict__ Aq, const float* __restrict__ Ak, const float* __restrict__ Av,
    const float* __restrict__ Wq, const float* __restrict__ Wk, const float* __restrict__ Wv,
    const float* __restrict__ bq, const float* __restrict__ bk, const float* __restrict__ bv,
    float* __restrict__ Cq, float* __restrict__ Ck, float* __restrict__ Cv)
{
    const float *A, *W, *bias; float* C; float scale;
    if (blockIdx.z == 0)      { A = Aq; W = Wq; bias = bq; C = Cq; scale = 0.17677669529663688f; }
    else if (blockIdx.z == 1) { A = Ak; W = Wk; bias = bk; C = Ck; scale = 1.0f; }
    else                      { A = Av; W = Wv; bias = bv; C = Cv; scale = 1.0f; }
    gemm128_body(A, W, bias, C, scale, blockIdx.y * 128, blockIdx.x * 128);
}

// ---------------------------------------------------------------------------
// Fused attention, fixed-max softmax. L1-minimized:
//  score phase (lane=k): struct via 8 LDS.128; p stored to P smem.
//  accumulate (lane=(qhat,oct)): 1 broadcast LDS p + 2 LDG.128 V +
//  2 LDS.128 ST per k -> 16 FMAs. No shuffles in hot loop.
// ---------------------------------------------------------------------------
__global__ void __launch_bounds__(NTHREADS, 2) attn_kernel(
    const float* __restrict__ qh, const float* __restrict__ ktr, const float* __restrict__ vh,
    const float* __restrict__ st_g, const void* __restrict__ kmask_raw,
    const float* __restrict__ wsk, const float* __restrict__ wsv, const float* __restrict__ bsv,
    float* __restrict__ ctx, float* __restrict__ scores0)
{
    extern __shared__ float sm[];
    float* QS = sm + OFF_QS;
    float* QW = sm + OFF_QW;
    float* P  = sm + OFF_P;
    float* ST = sm + OFF_ST;

    const int tid = threadIdx.x;
    const int h = tid >> 5, lane = tid & 31;     // warp = head
    const int qhat = lane >> 2, oct = lane & 3;  // accumulate identity
    const int b = blockIdx.x >> 6;
    const int q0 = (blockIdx.x & 63) * TQ;
    const int mask_is_byte = g_mask_is_byte;
    const unsigned char* km8 = (const unsigned char*)kmask_raw;
    const int* km32 = (const int*)kmask_raw;

    // staging identity: warp h stages q-row h
    const float* st_qrow = st_g + (((size_t)b * LSEQ + q0 + h) * LSEQ) * DS;
    float* st_dst = &ST[h * ST_Q];
    const int ek0 = (lane * 2) / DS;
    const int es0 = (lane * 2) % DS;

    const float* ktb = ktr + (size_t)b * DM * LSEQ + (size_t)(h * 32) * LSEQ;

    // ---- init: QS load, wsk->P (temp), zero QW & ST ----
    {
        const float4* qg4 = reinterpret_cast<const float4*>(qh + ((size_t)b * LSEQ + q0) * DM);
        for (int f = tid; f < TQ * DM / 4; f += NTHREADS) {
            int q = f >> 6, c4 = f & 63;
            float4 v = qg4[f];
            int hh = c4 >> 3, d = (c4 & 7) * 4;
            float* dst = &QS[(hh * TQ + q) * 32 + d];
            dst[0] = v.x; dst[1] = v.y; dst[2] = v.z; dst[3] = v.w;
        }
    }
    for (int i = tid; i < DS * DH; i += NTHREADS) P[i] = wsk[i];
    for (int i = tid; i < NH * TQ * 32; i += NTHREADS) QW[i] = 0.f;
    for (int i = tid; i < TQ * ST_Q; i += NTHREADS) ST[i] = 0.f;
    __syncthreads();

    // qwsk[h,q,s] = sum_d QS[h,q,d] * wsk[s,d]
    for (int i = tid; i < NH * TQ * DS; i += NTHREADS) {
        int hh = i / (TQ * DS);
        int r = i - hh * (TQ * DS);
        int q = r / DS;
        int s = r - q * DS;
        const float* qp = &QS[(hh * TQ + q) * 32];
        const float* wp = &P[s * 32];
        float a = 0.f;
#pragma unroll
        for (int d = 0; d < 32; d++) a += qp[d] * wp[d];
        QW[(hh * TQ + q) * 32 + s] = a;
    }
    __syncthreads();

    // ---- initial ST staging (coalesced LDG -> (k,s) walk STS, stride 36) ----
    float2 pre[15];
    {
        const float2* src = reinterpret_cast<const float2*>(st_qrow);
#pragma unroll
        for (int i = 0; i < 15; i++) pre[i] = src[i * 32 + lane];
    }
    {
        int kk = ek0, ss = es0;
#pragma unroll
        for (int i = 0; i < 15; i++) {
            st_dst[kk * ST_K + ss] = pre[i].x;
            int k2 = kk, s2 = ss + 1;
            if (s2 == DS) { s2 = 0; k2++; }
            st_dst[k2 * ST_K + s2] = pre[i].y;
            ss += 4; kk += 2;                 // e advances by 64 (= 2*30 + 4)
            if (ss >= DS) { ss -= DS; kk++; }
        }
    }
    __syncthreads();

    float acc[8], ps[8], lsum[TQ];
#pragma unroll
    for (int i = 0; i < 8; i++) { acc[i] = 0.f; ps[i] = 0.f; }
#pragma unroll
    for (int q = 0; q < TQ; q++) lsum[q] = 0.f;

    for (int kt = 0; kt < NKT; kt++) {
        const int k0 = kt * TK;

        if (kt + 1 < NKT) {
            const float2* src = reinterpret_cast<const float2*>(st_qrow + (size_t)(k0 + TK) * DS);
#pragma unroll
            for (int i = 0; i < 15; i++) pre[i] = src[i * 32 + lane];
        }

        const int midx = b * LSEQ + k0 + lane;
        const bool masked = mask_is_byte ? (km8[midx] != 0) : (km32[midx] != 0);

        float kreg[32];
        {
            const float* kp = ktb + k0 + lane;
#pragma unroll
            for (int d = 0; d < 32; d++) kreg[d] = kp[(size_t)d * LSEQ];
        }

        // ---- score phase: lane = k ----
#pragma unroll
        for (int q = 0; q < TQ; q++) {
            const float4* qv = reinterpret_cast<const float4*>(&QS[(h * TQ + q) * 32]);
            float s = 0.f;
#pragma unroll
            for (int d4 = 0; d4 < 8; d4++) {
                float4 qd = qv[d4];
                s += qd.x * kreg[d4 * 4] + qd.y * kreg[d4 * 4 + 1]
                   + qd.z * kreg[d4 * 4 + 2] + qd.w * kreg[d4 * 4 + 3];
            }
            const float4* qwv = reinterpret_cast<const float4*>(&QW[(h * TQ + q) * 32]);
            const float4* stp = reinterpret_cast<const float4*>(&ST[q * ST_Q + lane * ST_K]);
#pragma unroll
            for (int s4 = 0; s4 < 8; s4++) {   // s=30,31 pads zero in QW
                float4 ww = qwv[s4];
                float4 sv = stp[s4];
                s += ww.x * sv.x + ww.y * sv.y + ww.z * sv.z + ww.w * sv.w;
            }
            if (masked) s = -1e30f;

            float p = __expf(s);
            lsum[q] += p;
            P[(h * TQ + q) * P_STR + lane] = p;
            if (h == 0)
                scores0[((size_t)(b * LSEQ + q0 + q)) * LSEQ + k0 + lane] = p;
        }
        __syncwarp();

        // ---- accumulate: lane = (qhat, oct) ----
        {
            const float* prow = &P[(h * TQ + qhat) * P_STR];
            const float* strow = &ST[qhat * ST_Q + oct * 8];
            const float* vrow = vh + ((size_t)(b * LSEQ + k0)) * DM + h * 32 + oct * 8;
#pragma unroll 4
            for (int k = 0; k < TK; k++) {
                float p = prow[k];
                float4 v0 = *reinterpret_cast<const float4*>(&vrow[(size_t)k * DM]);
                float4 v1 = *reinterpret_cast<const float4*>(&vrow[(size_t)k * DM + 4]);
                float4 s0 = *reinterpret_cast<const float4*>(&strow[k * ST_K]);
                float4 s1 = *reinterpret_cast<const float4*>(&strow[k * ST_K + 4]);
                acc[0] += p * v0.x; acc[1] += p * v0.y; acc[2] += p * v0.z; acc[3] += p * v0.w;
                acc[4] += p * v1.x; acc[5] += p * v1.y; acc[6] += p * v1.z; acc[7] += p * v1.w;
                ps[0] += p * s0.x; ps[1] += p * s0.y; ps[2] += p * s0.z; ps[3] += p * s0.w;
                ps[4] += p * s1.x; ps[5] += p * s1.y; ps[6] += p * s1.z; ps[7] += p * s1.w;
            }
        }

        __syncthreads();
        if (kt + 1 < NKT) {
            int kk = ek0, ss = es0;
#pragma unroll
            for (int i = 0; i < 15; i++) {
                st_dst[kk * ST_K + ss] = pre[i].x;
                int k2 = kk, s2 = ss + 1;
                if (s2 == DS) { s2 = 0; k2++; }
                st_dst[k2 * ST_K + s2] = pre[i].y;
                ss += 4; kk += 2;
                if (ss >= DS) { ss -= DS; kk++; }
            }
            __syncthreads();
        }
    }

    // ---- final row-sum reduction (every lane ends with all 8 sums) ----
#pragma unroll
    for (int q = 0; q < TQ; q++) {
        float l = lsum[q];
#pragma unroll
        for (int off = 16; off; off >>= 1)
            l += __shfl_xor_sync(0xffffffffu, l, off);
        lsum[q] = l;
    }

    // ---- epilogue: ctx = (acc + ps@wsv)/l + bsv ----
    __syncthreads();
    for (int i = tid; i < DS * DH; i += NTHREADS) QS[i] = wsv[i];  // QS dead
    // ps -> P rows (own warp's rows; pads s=30,31 land harmlessly in row)
#pragma unroll
    for (int ss = 0; ss < 8; ss++)
        P[(h * TQ + qhat) * P_STR + oct * 8 + ss] = ps[ss];
    __syncthreads();

    float linv = 0.f;
#pragma unroll
    for (int q = 0; q < TQ; q++)
        if (qhat == q) linv = 1.f / lsum[q];

    float c[8];
#pragma unroll
    for (int dd = 0; dd < 8; dd++) c[dd] = acc[dd];
    {
        const float* prow = &P[(h * TQ + qhat) * P_STR];
#pragma unroll
        for (int s = 0; s < DS; s++) {
            float pv = prow[s];
            const float* wrow = &QS[s * 32 + oct * 8];
#pragma unroll
            for (int dd = 0; dd < 8; dd++) c[dd] += pv * wrow[dd];
        }
    }
#pragma unroll
    for (int dd = 0; dd < 8; dd++) c[dd] = c[dd] * linv + bsv[oct * 8 + dd];

    float* outp = &ctx[((size_t)(b * LSEQ + q0 + qhat)) * DM + h * 32 + oct * 8];
    float4 o0 = { c[0], c[1], c[2], c[3] };
    float4 o1 = { c[4], c[5], c[6], c[7] };
    reinterpret_cast<float4*>(outp)[0] = o0;
    reinterpret_cast<float4*>(outp)[1] = o1;
}

// ---------------------------------------------------------------------------
__global__ void __launch_bounds__(256) normalize_rows(
    const float* __restrict__ P, float* __restrict__ O)
{
    const int row = blockIdx.x;
    const float* s = P + (size_t)row * LSEQ;
    float* o = O + (size_t)row * LSEQ;
    const int t = threadIdx.x;

    float a = s[t], b = s[t + 256];
    float sum = a + b;
    __shared__ float red[8];
#pragma unroll
    for (int off = 16; off; off >>= 1) sum += __shfl_xor_sync(0xffffffffu, sum, off);
    if ((t & 31) == 0) red[t >> 5] = sum;
    __syncthreads();
    float sAll = 0.f;
#pragma unroll
    for (int i = 0; i < 8; i++) sAll += red[i];
    float inv = 1.f / sAll;
    o[t] = a * inv;
    o[t + 256] = b * inv;
}

// ---------------------------------------------------------------------------
extern "C" void kernel_launch(void* const* d_in, const int* in_sizes, int n_in,
                              void* d_out, int out_size)
{
    const float* key   = (const float*)d_in[0];
    const float* value = (const float*)d_in[1];
    const float* query = (const float*)d_in[2];

    const float* structure;
    const void*  kmaskp;
    if (in_sizes[3] == BSZ * LSEQ) {
        kmaskp    = d_in[3];
        structure = (const float*)d_in[4];
    } else {
        structure = (const float*)d_in[3];
        kmaskp    = d_in[4];
    }

    const float* wq  = (const float*)d_in[5];
    const float* bq  = (const float*)d_in[6];
    const float* wk  = (const float*)d_in[7];
    const float* bk  = (const float*)d_in[8];
    const float* wv  = (const float*)d_in[9];
    const float* bv  = (const float*)d_in[10];
    const float* wsk = (const float*)d_in[11];
    // d_in[12] = bsk: softmax-invariant, dropped.
    const float* wsv = (const float*)d_in[13];
    const float* bsv = (const float*)d_in[14];
    const float* wf  = (const float*)d_in[15];
    const float* bf  = (const float*)d_in[16];

    float* out = (float*)d_out;
    float* fin = out + (size_t)BSZ * LSEQ * DM;

    float* scratch = nullptr;
    cudaGetSymbolAddress((void**)&scratch, g_scratch);
    float* qh  = scratch;
    float* kh  = qh + (size_t)BSZ * LSEQ * DM;
    float* vh  = kh + (size_t)BSZ * LSEQ * DM;
    float* ctx = vh + (size_t)BSZ * LSEQ * DM;
    float* ktr = ctx + (size_t)BSZ * LSEQ * DM;
    float* sc0 = ktr + (size_t)BSZ * LSEQ * DM;

    detect_mask_kernel<<<1, 256>>>((const unsigned char*)kmaskp, BSZ * LSEQ);

    qkv_gemm<<<dim3(2, 32, 3), 256>>>(query, key, value,
                                      wq, wk, wv, bq, bk, bv,
                                      qh, kh, vh);

    transpose_k<<<dim3(16, 8, 8), dim3(32, 8)>>>(kh, ktr);

    cudaFuncSetAttribute(attn_kernel, cudaFuncAttributeMaxDynamicSharedMemorySize, SMEM_BYTES);
    attn_kernel<<<BSZ * (LSEQ / TQ), NTHREADS, SMEM_BYTES>>>(
        qh, ktr, vh, structure, kmaskp, wsk, wsv, bsv, ctx, sc0);

    normalize_rows<<<BSZ * LSEQ, 256>>>(sc0, fin);
    gemm128<<<dim3(2, 32), 256>>>(ctx, wf, bf, out, 1.0f);
}

// round 11
// speedup vs baseline: 1.1181x; 1.1181x over previous
#include <cuda_runtime.h>
#include <math.h>

#define BSZ 8
#define LSEQ 512
#define DM 256
#define NH 8
#define DH 32
#define DS 30

#define TQ 8       // q rows per CTA; warp w is head w AND q-row w (role switch)
#define TK 32
#define NKT (LSEQ / TK)
#define NTHREADS 256

#define ST_K 31               // [k][s] stride (banks s-k, conflict-free)
#define ST_Q (32 * ST_K)      // 992 per q-row
#define PT_Q 289              // Sqk [q][k*9+h], q-stride 32*9+1
#define P2R 33                // p rows [(q*8+h)][33]

// ---- attn dynamic smem layout (float offsets) ----
#define OFF_QS  0              // [8h][8q][32]  = 2048
#define OFF_QW  2048           // [8h][8q][32]  = 2048 (qwsk, s padded 30->32 zeros)
#define OFF_ST  4096           // 8q * 992      = 7936
#define OFF_PT  12032          // 8 * 289       = 2312
#define OFF_P2  14344          // 64 * 33       = 2112
#define OFF_PS  16456          // 64 * 33       = 2112 (epilogue ps)
#define OFF_WSK 18568          // 960
#define OFF_WSV 19528          // 30*33 = 990
#define OFF_LS  20518          // [8q*9+8h] = 80
#define SMEM_FLOATS 20608
#define SMEM_BYTES (SMEM_FLOATS * 4)

// scratch: qh, kh, vh, ctx, ktr (1M fl each) + scores0 (2M fl)
__device__ float g_scratch[5 * BSZ * LSEQ * DM + BSZ * LSEQ * LSEQ];
__device__ int g_mask_is_byte;

// ---------------------------------------------------------------------------
__global__ void detect_mask_kernel(const unsigned char* __restrict__ m, int nbytes)
{
    __shared__ int any;
    if (threadIdx.x == 0) any = 0;
    __syncthreads();
    int local = 0;
    for (int i = threadIdx.x; i < nbytes; i += blockDim.x)
        if ((i & 3) != 0 && m[i] != 0) local = 1;
    if (local) atomicOr(&any, 1);
    __syncthreads();
    if (threadIdx.x == 0) g_mask_is_byte = any;
}

// ---------------------------------------------------------------------------
// K transpose: ktr[b][n][m] = kh[b*512+m][n]
// ---------------------------------------------------------------------------
__global__ void __launch_bounds__(256) transpose_k(
    const float* __restrict__ kh, float* __restrict__ ktr)
{
    __shared__ float t[32][33];
    const int b = blockIdx.z;
    const int m0 = blockIdx.x * 32, n0 = blockIdx.y * 32;
    const int tx = threadIdx.x, ty = threadIdx.y;

    for (int r = ty; r < 32; r += 8)
        t[r][tx] = kh[(size_t)(b * LSEQ + m0 + r) * DM + n0 + tx];
    __syncthreads();
    for (int r = ty; r < 32; r += 8)
        ktr[(size_t)b * DM * LSEQ + (size_t)(n0 + r) * LSEQ + m0 + tx] = t[tx][r];
}

// ---------------------------------------------------------------------------
// SGEMM 128x128 tile, 256 threads, 8x8 microtile, double-buffered.
// ---------------------------------------------------------------------------
__device__ __forceinline__ void gemm128_body(
    const float* __restrict__ A, const float* __restrict__ W,
    const float* __restrict__ bias, float* __restrict__ C, float scale,
    int m0, int n0)
{
    __shared__ float As[2][8][128];
    __shared__ float Bs[2][8][128];

    const int tid = threadIdx.x;
    const int am = tid >> 1;
    const int ak = (tid & 1) * 4;
    const int br = tid >> 5;
    const int bc = (tid & 31) * 4;
    const int tx = tid & 15, ty = tid >> 4;

    float4 av = *reinterpret_cast<const float4*>(&A[(size_t)(m0 + am) * 256 + ak]);
    float4 bv = *reinterpret_cast<const float4*>(&W[(size_t)br * 256 + n0 + bc]);

    As[0][ak + 0][am] = av.x; As[0][ak + 1][am] = av.y;
    As[0][ak + 2][am] = av.z; As[0][ak + 3][am] = av.w;
    *reinterpret_cast<float4*>(&Bs[0][br][bc]) = bv;
    __syncthreads();

    float acc[8][8] = {};
    int buf = 0;

    for (int k0 = 0; k0 < 256; k0 += 8) {
        const bool more = (k0 + 8 < 256);
        if (more) {
            av = *reinterpret_cast<const float4*>(&A[(size_t)(m0 + am) * 256 + k0 + 8 + ak]);
            bv = *reinterpret_cast<const float4*>(&W[(size_t)(k0 + 8 + br) * 256 + n0 + bc]);
        }
#pragma unroll
        for (int kk = 0; kk < 8; kk++) {
            float a[8], b[8];
            *reinterpret_cast<float4*>(&a[0]) = *reinterpret_cast<const float4*>(&As[buf][kk][ty * 8]);
            *reinterpret_cast<float4*>(&a[4]) = *reinterpret_cast<const float4*>(&As[buf][kk][ty * 8 + 4]);
            *reinterpret_cast<float4*>(&b[0]) = *reinterpret_cast<const float4*>(&Bs[buf][kk][tx * 8]);
            *reinterpret_cast<float4*>(&b[4]) = *reinterpret_cast<const float4*>(&Bs[buf][kk][tx * 8 + 4]);
#pragma unroll
            for (int i = 0; i < 8; i++)
#pragma unroll
                for (int j = 0; j < 8; j++) acc[i][j] += a[i] * b[j];
        }
        if (more) {
            buf ^= 1;
            As[buf][ak + 0][am] = av.x; As[buf][ak + 1][am] = av.y;
            As[buf][ak + 2][am] = av.z; As[buf][ak + 3][am] = av.w;
            *reinterpret_cast<float4*>(&Bs[buf][br][bc]) = bv;
            __syncthreads();
        }
    }

    float bb[8];
#pragma unroll
    for (int j = 0; j < 8; j++) bb[j] = bias[n0 + tx * 8 + j];
#pragma unroll
    for (int i = 0; i < 8; i++) {
        float4 c0, c1;
        c0.x = (acc[i][0] + bb[0]) * scale; c0.y = (acc[i][1] + bb[1]) * scale;
        c0.z = (acc[i][2] + bb[2]) * scale; c0.w = (acc[i][3] + bb[3]) * scale;
        c1.x = (acc[i][4] + bb[4]) * scale; c1.y = (acc[i][5] + bb[5]) * scale;
        c1.z = (acc[i][6] + bb[6]) * scale; c1.w = (acc[i][7] + bb[7]) * scale;
        float* cp = &C[(size_t)(m0 + ty * 8 + i) * 256 + n0 + tx * 8];
        reinterpret_cast<float4*>(cp)[0] = c0;
        reinterpret_cast<float4*>(cp)[1] = c1;
    }
}

__global__ void __launch_bounds__(256) gemm128(
    const float* __restrict__ A, const float* __restrict__ W,
    const float* __restrict__ bias, float* __restrict__ C, float scale)
{
    gemm128_body(A, W, bias, C, scale, blockIdx.y * 128, blockIdx.x * 128);
}

__global__ void __launch_bounds__(256) qkv_gemm(
    const float* __restrict__ Aq, const float* __restrict__ Ak, const float* __restrict__ Av,
    const float* __restrict__ Wq, const float* __restrict__ Wk, const float* __restrict__ Wv,
    const float* __restrict__ bq, const float* __restrict__ bk, const float* __restrict__ bv,
    float* __restrict__ Cq, float* __restrict__ Ck, float* __restrict__ Cv)
{
    const float *A, *W, *bias; float* C; float scale;
    if (blockIdx.z == 0)      { A = Aq; W = Wq; bias = bq; C = Cq; scale = 0.17677669529663688f; }
    else if (blockIdx.z == 1) { A = Ak; W = Wk; bias = bk; C = Ck; scale = 1.0f; }
    else                      { A = Av; W = Wv; bias = bv; C = Cv; scale = 1.0f; }
    gemm128_body(A, W, bias, C, scale, blockIdx.y * 128, blockIdx.x * 128);
}

// ---------------------------------------------------------------------------
// Fused attention, fixed-max softmax, ROLE-SWITCHING warps:
//   QK    (warp=head h=w, lane=k): Sqk -> PT
//   BIAS  (warp=q-row q=w, lane=k): struct row read ONCE, bias for all 8 h,
//          p=exp -> P2
//   ACC-V (warp=h=w, lane=(q,oct)): acc[8d] += p*V (LDG), lsum folded in
//   ACC-PS(warp=q=w, lane=s):       ps[8h]  += p*struct
// All smem patterns bank-verified conflict-free (strides 31/289/33).
// ---------------------------------------------------------------------------
__global__ void __launch_bounds__(NTHREADS, 2) attn_kernel(
    const float* __restrict__ qh, const float* __restrict__ ktr, const float* __restrict__ vh,
    const float* __restrict__ st_g, const void* __restrict__ kmask_raw,
    const float* __restrict__ wsk, const float* __restrict__ wsv, const float* __restrict__ bsv,
    float* __restrict__ ctx, float* __restrict__ scores0)
{
    extern __shared__ float sm[];
    float* QS  = sm + OFF_QS;
    float* QW  = sm + OFF_QW;
    float* ST  = sm + OFF_ST;
    float* PT  = sm + OFF_PT;
    float* P2  = sm + OFF_P2;
    float* PS  = sm + OFF_PS;
    float* WSK = sm + OFF_WSK;
    float* WSV = sm + OFF_WSV;
    float* LS  = sm + OFF_LS;

    const int tid = threadIdx.x;
    const int w = tid >> 5, lane = tid & 31;
    const int aq = lane >> 2, aoct = lane & 3;    // ACC-V lane identity
    const int b = blockIdx.x >> 6;
    const int q0 = (blockIdx.x & 63) * TQ;
    const int mask_is_byte = g_mask_is_byte;
    const unsigned char* km8 = (const unsigned char*)kmask_raw;
    const int* km32 = (const int*)kmask_raw;

    // struct staging: warp w stages q-row w (coalesced LDG + (k,s) walk scatter)
    const float* st_qrow = st_g + (((size_t)b * LSEQ + q0 + w) * LSEQ) * DS;
    float* st_dst = ST + w * ST_Q;
    const int ek0 = (lane * 2) / DS;
    const int es0 = (lane * 2) % DS;

    const float* ktb = ktr + (size_t)b * DM * LSEQ + (size_t)(w * DH) * LSEQ;

    // ---- init: QS, WSK, WSV, zero QW ----
    {
        const float4* qg4 = reinterpret_cast<const float4*>(qh + ((size_t)b * LSEQ + q0) * DM);
        for (int f = tid; f < TQ * DM / 4; f += NTHREADS) {
            int q = f >> 6, c4 = f & 63;
            float4 v = qg4[f];
            int hh = c4 >> 3, d = (c4 & 7) * 4;
            float* dst = &QS[(hh * TQ + q) * 32 + d];
            dst[0] = v.x; dst[1] = v.y; dst[2] = v.z; dst[3] = v.w;
        }
    }
    for (int i = tid; i < DS * DH; i += NTHREADS) WSK[i] = wsk[i];
    for (int i = tid; i < DS * DH; i += NTHREADS) {
        int s = i >> 5, d = i & 31;
        WSV[s * 33 + d] = wsv[i];
    }
    for (int i = tid; i < NH * TQ * 32; i += NTHREADS) QW[i] = 0.f;
    __syncthreads();

    // qwsk[h,q,s] = sum_d QS[h,q,d] * wsk[s,d]
    for (int i = tid; i < NH * TQ * DS; i += NTHREADS) {
        int hh = i / (TQ * DS);
        int r = i - hh * (TQ * DS);
        int q = r / DS;
        int s = r - q * DS;
        const float* qp = &QS[(hh * TQ + q) * 32];
        const float* wp = &WSK[s * 32];
        float a = 0.f;
#pragma unroll
        for (int d = 0; d < 32; d++) a += qp[d] * wp[d];
        QW[(hh * TQ + q) * 32 + s] = a;
    }

    // ---- initial ST staging for tile 0 ----
    float2 pre[15];
    {
        const float2* src = reinterpret_cast<const float2*>(st_qrow);
#pragma unroll
        for (int i = 0; i < 15; i++) pre[i] = src[i * 32 + lane];
    }
    {
        int kk = ek0, ss = es0;
#pragma unroll
        for (int i = 0; i < 15; i++) {
            st_dst[kk * ST_K + ss] = pre[i].x;
            int k2 = kk, s2 = ss + 1;
            if (s2 == DS) { s2 = 0; k2++; }
            st_dst[k2 * ST_K + s2] = pre[i].y;
            ss += 4; kk += 2;                 // e advances by 64 (= 2*30 + 4)
            if (ss >= DS) { ss -= DS; kk++; }
        }
    }
    __syncthreads();   // QW + ST(0) ready

    float acc[8], psp[8];
    float lsum = 0.f;
#pragma unroll
    for (int i = 0; i < 8; i++) { acc[i] = 0.f; psp[i] = 0.f; }

    for (int kt = 0; kt < NKT; kt++) {
        const int k0 = kt * TK;

        // ======== QK phase: warp = head w, lane = k ========
        {
            float kreg[32];
            const float* kp = ktb + k0 + lane;
#pragma unroll
            for (int d = 0; d < 32; d++) kreg[d] = kp[(size_t)d * LSEQ];

#pragma unroll
            for (int q = 0; q < TQ; q++) {
                const float4* qv = reinterpret_cast<const float4*>(&QS[(w * TQ + q) * 32]);
                float s = 0.f;
#pragma unroll
                for (int d4 = 0; d4 < 8; d4++) {
                    float4 qd = qv[d4];
                    s += qd.x * kreg[d4 * 4] + qd.y * kreg[d4 * 4 + 1]
                       + qd.z * kreg[d4 * 4 + 2] + qd.w * kreg[d4 * 4 + 3];
                }
                PT[q * PT_Q + lane * 9 + w] = s;
            }
        }
        __syncthreads();   // (1) Sqk visible

        // ======== BIAS phase: warp = q-row w, lane = k ========
        {
            const int midx = b * LSEQ + k0 + lane;
            const bool masked = mask_is_byte ? (km8[midx] != 0) : (km32[midx] != 0);

            float sv[32];
            const float* stq = ST + w * ST_Q + lane * ST_K;
#pragma unroll
            for (int s = 0; s < DS; s++) sv[s] = stq[s];
            sv[30] = 0.f; sv[31] = 0.f;

            float pq0 = 0.f;
#pragma unroll
            for (int h2 = 0; h2 < NH; h2++) {
                const float4* qw4 = reinterpret_cast<const float4*>(&QW[(h2 * TQ + w) * 32]);
                float bias = 0.f;
#pragma unroll
                for (int s4 = 0; s4 < 8; s4++) {
                    float4 ww = qw4[s4];
                    bias += ww.x * sv[s4 * 4] + ww.y * sv[s4 * 4 + 1]
                          + ww.z * sv[s4 * 4 + 2] + ww.w * sv[s4 * 4 + 3];
                }
                float sc = PT[w * PT_Q + lane * 9 + h2] + bias;
                float p = masked ? 0.f : __expf(sc);
                if (h2 == 0) pq0 = p;
                P2[(w * 8 + h2) * P2R + lane] = p;
            }
            scores0[((size_t)(b * LSEQ + q0 + w)) * LSEQ + k0 + lane] = pq0;
        }
        __syncthreads();   // (2) p visible

        // prefetch next struct slice (hidden under ACC work)
        if (kt + 1 < NKT) {
            const float2* src = reinterpret_cast<const float2*>(st_qrow + (size_t)(k0 + TK) * DS);
#pragma unroll
            for (int i = 0; i < 15; i++) pre[i] = src[i * 32 + lane];
        }

        // ======== ACC-V: warp = head w, lane = (aq, aoct) ========
        {
            const float* vbase = vh + ((size_t)(b * LSEQ + k0)) * DM + w * DH + aoct * 8;
            const float* prow = &P2[(aq * 8 + w) * P2R];
#pragma unroll 4
            for (int k = 0; k < TK; k++) {
                float p = prow[k];
                float4 v0 = *reinterpret_cast<const float4*>(vbase + (size_t)k * DM);
                float4 v1 = *reinterpret_cast<const float4*>(vbase + (size_t)k * DM + 4);
                acc[0] += p * v0.x; acc[1] += p * v0.y; acc[2] += p * v0.z; acc[3] += p * v0.w;
                acc[4] += p * v1.x; acc[5] += p * v1.y; acc[6] += p * v1.z; acc[7] += p * v1.w;
                lsum += p;
            }
        }

        // ======== ACC-PS: warp = q-row w, lane = s ========
        {
            const float* stq2 = ST + w * ST_Q + lane;
            const float* pbase = &P2[(w * 8) * P2R];
#pragma unroll 4
            for (int k = 0; k < TK; k++) {
                float svk = stq2[k * ST_K];
#pragma unroll
                for (int h2 = 0; h2 < NH; h2++)
                    psp[h2] += pbase[h2 * P2R + k] * svk;
            }
        }

        __syncthreads();   // (3) done reading ST/P2

        // commit prefetched struct tile
        if (kt + 1 < NKT) {
            int kk = ek0, ss = es0;
#pragma unroll
            for (int i = 0; i < 15; i++) {
                st_dst[kk * ST_K + ss] = pre[i].x;
                int k2 = kk, s2 = ss + 1;
                if (s2 == DS) { s2 = 0; k2++; }
                st_dst[k2 * ST_K + s2] = pre[i].y;
                ss += 4; kk += 2;
                if (ss >= DS) { ss -= DS; kk++; }
            }
        }
        // visibility of commit to next BIAS is covered by next iteration's sync (1)
    }

    // ---- epilogue ----
    if (aoct == 0) LS[aq * 9 + w] = lsum;        // lsum for (h=w, q=aq)
    if (lane < DS) {
#pragma unroll
        for (int h2 = 0; h2 < NH; h2++)
            PS[(w * 8 + h2) * P2R + lane] = psp[h2];   // ps for (q=w, h2, s=lane)
    }
    __syncthreads();

    // final: warp = head w, lane = (aq, aoct)
    {
        float linv = 1.f / LS[aq * 9 + w];
        float c[8];
#pragma unroll
        for (int j = 0; j < 8; j++) c[j] = acc[j];

        const float* psrow = &PS[(aq * 8 + w) * P2R];
#pragma unroll
        for (int s = 0; s < DS; s++) {
            float pv = psrow[s];
            const float* wr = &WSV[s * 33 + aoct * 8];
#pragma unroll
            for (int j = 0; j < 8; j++) c[j] += pv * wr[j];
        }
#pragma unroll
        for (int j = 0; j < 8; j++) c[j] = c[j] * linv + bsv[aoct * 8 + j];

        float* outp = &ctx[((size_t)(b * LSEQ + q0 + aq)) * DM + w * DH + aoct * 8];
        float4 o0 = { c[0], c[1], c[2], c[3] };
        float4 o1 = { c[4], c[5], c[6], c[7] };
        reinterpret_cast<float4*>(outp)[0] = o0;
        reinterpret_cast<float4*>(outp)[1] = o1;
    }
}

// ---------------------------------------------------------------------------
__global__ void __launch_bounds__(256) normalize_rows(
    const float* __restrict__ P, float* __restrict__ O)
{
    const int row = blockIdx.x;
    const float* s = P + (size_t)row * LSEQ;
    float* o = O + (size_t)row * LSEQ;
    const int t = threadIdx.x;

    float a = s[t], b = s[t + 256];
    float sum = a + b;
    __shared__ float red[8];
#pragma unroll
    for (int off = 16; off; off >>= 1) sum += __shfl_xor_sync(0xffffffffu, sum, off);
    if ((t & 31) == 0) red[t >> 5] = sum;
    __syncthreads();
    float sAll = 0.f;
#pragma unroll
    for (int i = 0; i < 8; i++) sAll += red[i];
    float inv = 1.f / sAll;
    o[t] = a * inv;
    o[t + 256] = b * inv;
}

// ---------------------------------------------------------------------------
extern "C" void kernel_launch(void* const* d_in, const int* in_sizes, int n_in,
                              void* d_out, int out_size)
{
    const float* key   = (const float*)d_in[0];
    const float* value = (const float*)d_in[1];
    const float* query = (const float*)d_in[2];

    const float* structure;
    const void*  kmaskp;
    if (in_sizes[3] == BSZ * LSEQ) {
        kmaskp    = d_in[3];
        structure = (const float*)d_in[4];
    } else {
        structure = (const float*)d_in[3];
        kmaskp    = d_in[4];
    }

    const float* wq  = (const float*)d_in[5];
    const float* bq  = (const float*)d_in[6];
    const float* wk  = (const float*)d_in[7];
    const float* bk  = (const float*)d_in[8];
    const float* wv  = (const float*)d_in[9];
    const float* bv  = (const float*)d_in[10];
    const float* wsk = (const float*)d_in[11];
    // d_in[12] = bsk: softmax-invariant, dropped.
    const float* wsv = (const float*)d_in[13];
    const float* bsv = (const float*)d_in[14];
    const float* wf  = (const float*)d_in[15];
    const float* bf  = (const float*)d_in[16];

    float* out = (float*)d_out;
    float* fin = out + (size_t)BSZ * LSEQ * DM;

    float* scratch = nullptr;
    cudaGetSymbolAddress((void**)&scratch, g_scratch);
    float* qh  = scratch;
    float* kh  = qh + (size_t)BSZ * LSEQ * DM;
    float* vh  = kh + (size_t)BSZ * LSEQ * DM;
    float* ctx = vh + (size_t)BSZ * LSEQ * DM;
    float* ktr = ctx + (size_t)BSZ * LSEQ * DM;
    float* sc0 = ktr + (size_t)BSZ * LSEQ * DM;

    detect_mask_kernel<<<1, 256>>>((const unsigned char*)kmaskp, BSZ * LSEQ);

    qkv_gemm<<<dim3(2, 32, 3), 256>>>(query, key, value,
                                      wq, wk, wv, bq, bk, bv,
                                      qh, kh, vh);

    transpose_k<<<dim3(16, 8, 8), dim3(32, 8)>>>(kh, ktr);

    cudaFuncSetAttribute(attn_kernel, cudaFuncAttributeMaxDynamicSharedMemorySize, SMEM_BYTES);
    attn_kernel<<<BSZ * (LSEQ / TQ), NTHREADS, SMEM_BYTES>>>(
        qh, ktr, vh, structure, kmaskp, wsk, wsv, bsv, ctx, sc0);

    normalize_rows<<<BSZ * LSEQ, 256>>>(sc0, fin);
    gemm128<<<dim3(2, 32), 256>>>(ctx, wf, bf, out, 1.0f);
}

// round 12
// speedup vs baseline: 1.1385x; 1.0183x over previous
#include <cuda_runtime.h>
#include <math.h>

#define BSZ 8
#define LSEQ 512
#define DM 256
#define NH 8
#define DH 32
#define DS 30

#define TQ 8       // q rows per CTA; warp w is head w AND q-row w (role switch)
#define TK 32
#define NKT (LSEQ / TK)
#define NTHREADS 256

#define ST_K 31               // [k][s] stride (banks s-k, conflict-free)
#define ST_Q (32 * ST_K)      // 992 per q-row
#define PT_Q 289              // Sqk [q][k*9+h], q-stride 32*9+1
#define P2R 33                // p rows [(q*8+h)][33]
#define PB_K 12               // transposed p: [q][k][8h], k-stride 12 (16B-aligned, bank-cycling)
#define PB_Q (32 * PB_K)      // 384 per q

// ---- attn dynamic smem layout (float offsets) ----
#define OFF_QS  0              // [8h][8q][32]  = 2048
#define OFF_QW  2048           // [8h][8q][32]  = 2048 (qwsk, s padded 30->32 zeros)
#define OFF_ST  4096           // 8q * 992      = 7936
#define OFF_PT  12032          // 8 * 289       = 2312
#define OFF_P2  14344          // 64 * 33       = 2112
#define OFF_PS  16456          // 64 * 33       = 2112 (epilogue ps)
#define OFF_WSK 18568          // 960
#define OFF_WSV 19528          // 30*33 = 990
#define OFF_LS  20518          // 80
#define OFF_PB  20608          // 8 * 384 = 3072
#define SMEM_FLOATS 23680
#define SMEM_BYTES (SMEM_FLOATS * 4)

// scratch: qh, kh, vh, ctx, ktr (1M fl each) + scores0 (2M fl)
__device__ float g_scratch[5 * BSZ * LSEQ * DM + BSZ * LSEQ * LSEQ];
__device__ int g_mask_is_byte;

// ---------------------------------------------------------------------------
__global__ void detect_mask_kernel(const unsigned char* __restrict__ m, int nbytes)
{
    __shared__ int any;
    if (threadIdx.x == 0) any = 0;
    __syncthreads();
    int local = 0;
    for (int i = threadIdx.x; i < nbytes; i += blockDim.x)
        if ((i & 3) != 0 && m[i] != 0) local = 1;
    if (local) atomicOr(&any, 1);
    __syncthreads();
    if (threadIdx.x == 0) g_mask_is_byte = any;
}

// ---------------------------------------------------------------------------
// K transpose: ktr[b][n][m] = kh[b*512+m][n]
// ---------------------------------------------------------------------------
__global__ void __launch_bounds__(256) transpose_k(
    const float* __restrict__ kh, float* __restrict__ ktr)
{
    __shared__ float t[32][33];
    const int b = blockIdx.z;
    const int m0 = blockIdx.x * 32, n0 = blockIdx.y * 32;
    const int tx = threadIdx.x, ty = threadIdx.y;

    for (int r = ty; r < 32; r += 8)
        t[r][tx] = kh[(size_t)(b * LSEQ + m0 + r) * DM + n0 + tx];
    __syncthreads();
    for (int r = ty; r < 32; r += 8)
        ktr[(size_t)b * DM * LSEQ + (size_t)(n0 + r) * LSEQ + m0 + tx] = t[tx][r];
}

// ---------------------------------------------------------------------------
// SGEMM 128x128 tile, 256 threads, 8x8 microtile, double-buffered.
// ---------------------------------------------------------------------------
__device__ __forceinline__ void gemm128_body(
    const float* __restrict__ A, const float* __restrict__ W,
    const float* __restrict__ bias, float* __restrict__ C, float scale,
    int m0, int n0)
{
    __shared__ float As[2][8][128];
    __shared__ float Bs[2][8][128];

    const int tid = threadIdx.x;
    const int am = tid >> 1;
    const int ak = (tid & 1) * 4;
    const int br = tid >> 5;
    const int bc = (tid & 31) * 4;
    const int tx = tid & 15, ty = tid >> 4;

    float4 av = *reinterpret_cast<const float4*>(&A[(size_t)(m0 + am) * 256 + ak]);
    float4 bv = *reinterpret_cast<const float4*>(&W[(size_t)br * 256 + n0 + bc]);

    As[0][ak + 0][am] = av.x; As[0][ak + 1][am] = av.y;
    As[0][ak + 2][am] = av.z; As[0][ak + 3][am] = av.w;
    *reinterpret_cast<float4*>(&Bs[0][br][bc]) = bv;
    __syncthreads();

    float acc[8][8] = {};
    int buf = 0;

    for (int k0 = 0; k0 < 256; k0 += 8) {
        const bool more = (k0 + 8 < 256);
        if (more) {
            av = *reinterpret_cast<const float4*>(&A[(size_t)(m0 + am) * 256 + k0 + 8 + ak]);
            bv = *reinterpret_cast<const float4*>(&W[(size_t)(k0 + 8 + br) * 256 + n0 + bc]);
        }
#pragma unroll
        for (int kk = 0; kk < 8; kk++) {
            float a[8], b[8];
            *reinterpret_cast<float4*>(&a[0]) = *reinterpret_cast<const float4*>(&As[buf][kk][ty * 8]);
            *reinterpret_cast<float4*>(&a[4]) = *reinterpret_cast<const float4*>(&As[buf][kk][ty * 8 + 4]);
            *reinterpret_cast<float4*>(&b[0]) = *reinterpret_cast<const float4*>(&Bs[buf][kk][tx * 8]);
            *reinterpret_cast<float4*>(&b[4]) = *reinterpret_cast<const float4*>(&Bs[buf][kk][tx * 8 + 4]);
#pragma unroll
            for (int i = 0; i < 8; i++)
#pragma unroll
                for (int j = 0; j < 8; j++) acc[i][j] += a[i] * b[j];
        }
        if (more) {
            buf ^= 1;
            As[buf][ak + 0][am] = av.x; As[buf][ak + 1][am] = av.y;
            As[buf][ak + 2][am] = av.z; As[buf][ak + 3][am] = av.w;
            *reinterpret_cast<float4*>(&Bs[buf][br][bc]) = bv;
            __syncthreads();
        }
    }

    float bb[8];
#pragma unroll
    for (int j = 0; j < 8; j++) bb[j] = bias[n0 + tx * 8 + j];
#pragma unroll
    for (int i = 0; i < 8; i++) {
        float4 c0, c1;
        c0.x = (acc[i][0] + bb[0]) * scale; c0.y = (acc[i][1] + bb[1]) * scale;
        c0.z = (acc[i][2] + bb[2]) * scale; c0.w = (acc[i][3] + bb[3]) * scale;
        c1.x = (acc[i][4] + bb[4]) * scale; c1.y = (acc[i][5] + bb[5]) * scale;
        c1.z = (acc[i][6] + bb[6]) * scale; c1.w = (acc[i][7] + bb[7]) * scale;
        float* cp = &C[(size_t)(m0 + ty * 8 + i) * 256 + n0 + tx * 8];
        reinterpret_cast<float4*>(cp)[0] = c0;
        reinterpret_cast<float4*>(cp)[1] = c1;
    }
}

__global__ void __launch_bounds__(256) gemm128(
    const float* __restrict__ A, const float* __restrict__ W,
    const float* __restrict__ bias, float* __restrict__ C, float scale)
{
    gemm128_body(A, W, bias, C, scale, blockIdx.y * 128, blockIdx.x * 128);
}

__global__ void __launch_bounds__(256) qkv_gemm(
    const float* __restrict__ Aq, const float* __restrict__ Ak, const float* __restrict__ Av,
    const float* __restrict__ Wq, const float* __restrict__ Wk, const float* __restrict__ Wv,
    const float* __restrict__ bq, const float* __restrict__ bk, const float* __restrict__ bv,
    float* __restrict__ Cq, float* __restrict__ Ck, float* __restrict__ Cv)
{
    const float *A, *W, *bias; float* C; float scale;
    if (blockIdx.z == 0)      { A = Aq; W = Wq; bias = bq; C = Cq; scale = 0.17677669529663688f; }
    else if (blockIdx.z == 1) { A = Ak; W = Wk; bias = bk; C = Ck; scale = 1.0f; }
    else                      { A = Av; W = Wv; bias = bv; C = Cv; scale = 1.0f; }
    gemm128_body(A, W, bias, C, scale, blockIdx.y * 128, blockIdx.x * 128);
}

// ---------------------------------------------------------------------------
// Fused attention, fixed-max softmax, role-switching warps:
//   QK    (warp=head w, lane=k): Sqk -> PT
//   BIAS  (warp=q-row w, lane=k): struct row once, bias for all 8 h, p=exp
//         -> P2 (scalar rows, for ACC-V) AND PB (transposed [q][k][8h], 2x
//         STS.128, for ACC-PS vector reads)
//   ACC-V (warp=h=w, lane=(q,oct)): acc[8d] += p*V (LDG), lsum folded in
//   ACC-PS(warp=q=w, lane=s): per k: 1 sv LDS + 2 broadcast LDS.128 of p[8h]
// ---------------------------------------------------------------------------
__global__ void __launch_bounds__(NTHREADS, 2) attn_kernel(
    const float* __restrict__ qh, const float* __restrict__ ktr, const float* __restrict__ vh,
    const float* __restrict__ st_g, const void* __restrict__ kmask_raw,
    const float* __restrict__ wsk, const float* __restrict__ wsv, const float* __restrict__ bsv,
    float* __restrict__ ctx, float* __restrict__ scores0)
{
    extern __shared__ float sm[];
    float* QS  = sm + OFF_QS;
    float* QW  = sm + OFF_QW;
    float* ST  = sm + OFF_ST;
    float* PT  = sm + OFF_PT;
    float* P2  = sm + OFF_P2;
    float* PS  = sm + OFF_PS;
    float* WSK = sm + OFF_WSK;
    float* WSV = sm + OFF_WSV;
    float* LS  = sm + OFF_LS;
    float* PB  = sm + OFF_PB;

    const int tid = threadIdx.x;
    const int w = tid >> 5, lane = tid & 31;
    const int aq = lane >> 2, aoct = lane & 3;    // ACC-V lane identity
    const int b = blockIdx.x >> 6;
    const int q0 = (blockIdx.x & 63) * TQ;
    const int mask_is_byte = g_mask_is_byte;
    const unsigned char* km8 = (const unsigned char*)kmask_raw;
    const int* km32 = (const int*)kmask_raw;

    // struct staging: warp w stages q-row w (coalesced LDG + (k,s) walk scatter)
    const float* st_qrow = st_g + (((size_t)b * LSEQ + q0 + w) * LSEQ) * DS;
    float* st_dst = ST + w * ST_Q;
    const int ek0 = (lane * 2) / DS;
    const int es0 = (lane * 2) % DS;

    const float* ktb = ktr + (size_t)b * DM * LSEQ + (size_t)(w * DH) * LSEQ;

    // ---- init: QS, WSK, WSV, zero QW ----
    {
        const float4* qg4 = reinterpret_cast<const float4*>(qh + ((size_t)b * LSEQ + q0) * DM);
        for (int f = tid; f < TQ * DM / 4; f += NTHREADS) {
            int q = f >> 6, c4 = f & 63;
            float4 v = qg4[f];
            int hh = c4 >> 3, d = (c4 & 7) * 4;
            float* dst = &QS[(hh * TQ + q) * 32 + d];
            dst[0] = v.x; dst[1] = v.y; dst[2] = v.z; dst[3] = v.w;
        }
    }
    for (int i = tid; i < DS * DH; i += NTHREADS) WSK[i] = wsk[i];
    for (int i = tid; i < DS * DH; i += NTHREADS) {
        int s = i >> 5, d = i & 31;
        WSV[s * 33 + d] = wsv[i];
    }
    for (int i = tid; i < NH * TQ * 32; i += NTHREADS) QW[i] = 0.f;
    __syncthreads();

    // qwsk[h,q,s] = sum_d QS[h,q,d] * wsk[s,d]
    for (int i = tid; i < NH * TQ * DS; i += NTHREADS) {
        int hh = i / (TQ * DS);
        int r = i - hh * (TQ * DS);
        int q = r / DS;
        int s = r - q * DS;
        const float* qp = &QS[(hh * TQ + q) * 32];
        const float* wp = &WSK[s * 32];
        float a = 0.f;
#pragma unroll
        for (int d = 0; d < 32; d++) a += qp[d] * wp[d];
        QW[(hh * TQ + q) * 32 + s] = a;
    }

    // ---- initial ST staging for tile 0 ----
    float2 pre[15];
    {
        const float2* src = reinterpret_cast<const float2*>(st_qrow);
#pragma unroll
        for (int i = 0; i < 15; i++) pre[i] = src[i * 32 + lane];
    }
    {
        int kk = ek0, ss = es0;
#pragma unroll
        for (int i = 0; i < 15; i++) {
            st_dst[kk * ST_K + ss] = pre[i].x;
            int k2 = kk, s2 = ss + 1;
            if (s2 == DS) { s2 = 0; k2++; }
            st_dst[k2 * ST_K + s2] = pre[i].y;
            ss += 4; kk += 2;                 // e advances by 64 (= 2*30 + 4)
            if (ss >= DS) { ss -= DS; kk++; }
        }
    }
    __syncthreads();   // QW + ST(0) ready

    float acc[8], psp[8];
    float lsum = 0.f;
#pragma unroll
    for (int i = 0; i < 8; i++) { acc[i] = 0.f; psp[i] = 0.f; }

    for (int kt = 0; kt < NKT; kt++) {
        const int k0 = kt * TK;

        // ======== QK phase: warp = head w, lane = k ========
        {
            float kreg[32];
            const float* kp = ktb + k0 + lane;
#pragma unroll
            for (int d = 0; d < 32; d++) kreg[d] = kp[(size_t)d * LSEQ];

#pragma unroll
            for (int q = 0; q < TQ; q++) {
                const float4* qv = reinterpret_cast<const float4*>(&QS[(w * TQ + q) * 32]);
                float s = 0.f;
#pragma unroll
                for (int d4 = 0; d4 < 8; d4++) {
                    float4 qd = qv[d4];
                    s += qd.x * kreg[d4 * 4] + qd.y * kreg[d4 * 4 + 1]
                       + qd.z * kreg[d4 * 4 + 2] + qd.w * kreg[d4 * 4 + 3];
                }
                PT[q * PT_Q + lane * 9 + w] = s;
            }
        }
        __syncthreads();   // (1) Sqk visible

        // ======== BIAS phase: warp = q-row w, lane = k ========
        {
            const int midx = b * LSEQ + k0 + lane;
            const bool masked = mask_is_byte ? (km8[midx] != 0) : (km32[midx] != 0);

            float sv[32];
            const float* stq = ST + w * ST_Q + lane * ST_K;
#pragma unroll
            for (int s = 0; s < DS; s++) sv[s] = stq[s];
            sv[30] = 0.f; sv[31] = 0.f;

            float pr[8];
#pragma unroll
            for (int h2 = 0; h2 < NH; h2++) {
                const float4* qw4 = reinterpret_cast<const float4*>(&QW[(h2 * TQ + w) * 32]);
                float bias = 0.f;
#pragma unroll
                for (int s4 = 0; s4 < 8; s4++) {
                    float4 ww = qw4[s4];
                    bias += ww.x * sv[s4 * 4] + ww.y * sv[s4 * 4 + 1]
                          + ww.z * sv[s4 * 4 + 2] + ww.w * sv[s4 * 4 + 3];
                }
                float sc = PT[w * PT_Q + lane * 9 + h2] + bias;
                float p = masked ? 0.f : __expf(sc);
                pr[h2] = p;
                P2[(w * 8 + h2) * P2R + lane] = p;
            }
            scores0[((size_t)(b * LSEQ + q0 + w)) * LSEQ + k0 + lane] = pr[0];

            // transposed copy for ACC-PS: PB[q=w][k=lane][8h], 2x STS.128
            float4 pa = { pr[0], pr[1], pr[2], pr[3] };
            float4 pb4 = { pr[4], pr[5], pr[6], pr[7] };
            float* pbdst = &PB[w * PB_Q + lane * PB_K];
            reinterpret_cast<float4*>(pbdst)[0] = pa;
            reinterpret_cast<float4*>(pbdst)[1] = pb4;
        }
        __syncthreads();   // (2) p visible

        // prefetch next struct slice (hidden under ACC work)
        if (kt + 1 < NKT) {
            const float2* src = reinterpret_cast<const float2*>(st_qrow + (size_t)(k0 + TK) * DS);
#pragma unroll
            for (int i = 0; i < 15; i++) pre[i] = src[i * 32 + lane];
        }

        // ======== ACC-V: warp = head w, lane = (aq, aoct) ========
        {
            const float* vbase = vh + ((size_t)(b * LSEQ + k0)) * DM + w * DH + aoct * 8;
            const float* prow = &P2[(aq * 8 + w) * P2R];
#pragma unroll 4
            for (int k = 0; k < TK; k++) {
                float p = prow[k];
                float4 v0 = *reinterpret_cast<const float4*>(vbase + (size_t)k * DM);
                float4 v1 = *reinterpret_cast<const float4*>(vbase + (size_t)k * DM + 4);
                acc[0] += p * v0.x; acc[1] += p * v0.y; acc[2] += p * v0.z; acc[3] += p * v0.w;
                acc[4] += p * v1.x; acc[5] += p * v1.y; acc[6] += p * v1.z; acc[7] += p * v1.w;
                lsum += p;
            }
        }

        // ======== ACC-PS: warp = q-row w, lane = s ========
        {
            const float* stq2 = ST + w * ST_Q + lane;
            const float* pbq = &PB[w * PB_Q];
#pragma unroll 4
            for (int k = 0; k < TK; k++) {
                float svk = stq2[k * ST_K];
                float4 p0 = *reinterpret_cast<const float4*>(&pbq[k * PB_K]);
                float4 p1 = *reinterpret_cast<const float4*>(&pbq[k * PB_K + 4]);
                psp[0] += p0.x * svk; psp[1] += p0.y * svk;
                psp[2] += p0.z * svk; psp[3] += p0.w * svk;
                psp[4] += p1.x * svk; psp[5] += p1.y * svk;
                psp[6] += p1.z * svk; psp[7] += p1.w * svk;
            }
        }

        __syncthreads();   // (3) done reading ST/P2/PB

        // commit prefetched struct tile
        if (kt + 1 < NKT) {
            int kk = ek0, ss = es0;
#pragma unroll
            for (int i = 0; i < 15; i++) {
                st_dst[kk * ST_K + ss] = pre[i].x;
                int k2 = kk, s2 = ss + 1;
                if (s2 == DS) { s2 = 0; k2++; }
                st_dst[k2 * ST_K + s2] = pre[i].y;
                ss += 4; kk += 2;
                if (ss >= DS) { ss -= DS; kk++; }
            }
        }
        // visibility of commit to next BIAS covered by next iteration's sync (1)
    }

    // ---- epilogue ----
    if (aoct == 0) LS[aq * 9 + w] = lsum;        // lsum for (h=w, q=aq)
    if (lane < DS) {
#pragma unroll
        for (int h2 = 0; h2 < NH; h2++)
            PS[(w * 8 + h2) * P2R + lane] = psp[h2];   // ps for (q=w, h2, s=lane)
    }
    __syncthreads();

    // final: warp = head w, lane = (aq, aoct)
    {
        float linv = 1.f / LS[aq * 9 + w];
        float c[8];
#pragma unroll
        for (int j = 0; j < 8; j++) c[j] = acc[j];

        const float* psrow = &PS[(aq * 8 + w) * P2R];
#pragma unroll
        for (int s = 0; s < DS; s++) {
            float pv = psrow[s];
            const float* wr = &WSV[s * 33 + aoct * 8];
#pragma unroll
            for (int j = 0; j < 8; j++) c[j] += pv * wr[j];
        }
#pragma unroll
        for (int j = 0; j < 8; j++) c[j] = c[j] * linv + bsv[aoct * 8 + j];

        float* outp = &ctx[((size_t)(b * LSEQ + q0 + aq)) * DM + w * DH + aoct * 8];
        float4 o0 = { c[0], c[1], c[2], c[3] };
        float4 o1 = { c[4], c[5], c[6], c[7] };
        reinterpret_cast<float4*>(outp)[0] = o0;
        reinterpret_cast<float4*>(outp)[1] = o1;
    }
}

// ---------------------------------------------------------------------------
__global__ void __launch_bounds__(256) normalize_rows(
    const float* __restrict__ P, float* __restrict__ O)
{
    const int row = blockIdx.x;
    const float* s = P + (size_t)row * LSEQ;
    float* o = O + (size_t)row * LSEQ;
    const int t = threadIdx.x;

    float a = s[t], b = s[t + 256];
    float sum = a + b;
    __shared__ float red[8];
#pragma unroll
    for (int off = 16; off; off >>= 1) sum += __shfl_xor_sync(0xffffffffu, sum, off);
    if ((t & 31) == 0) red[t >> 5] = sum;
    __syncthreads();
    float sAll = 0.f;
#pragma unroll
    for (int i = 0; i < 8; i++) sAll += red[i];
    float inv = 1.f / sAll;
    o[t] = a * inv;
    o[t + 256] = b * inv;
}

// ---------------------------------------------------------------------------
extern "C" void kernel_launch(void* const* d_in, const int* in_sizes, int n_in,
                              void* d_out, int out_size)
{
    const float* key   = (const float*)d_in[0];
    const float* value = (const float*)d_in[1];
    const float* query = (const float*)d_in[2];

    const float* structure;
    const void*  kmaskp;
    if (in_sizes[3] == BSZ * LSEQ) {
        kmaskp    = d_in[3];
        structure = (const float*)d_in[4];
    } else {
        structure = (const float*)d_in[3];
        kmaskp    = d_in[4];
    }

    const float* wq  = (const float*)d_in[5];
    const float* bq  = (const float*)d_in[6];
    const float* wk  = (const float*)d_in[7];
    const float* bk  = (const float*)d_in[8];
    const float* wv  = (const float*)d_in[9];
    const float* bv  = (const float*)d_in[10];
    const float* wsk = (const float*)d_in[11];
    // d_in[12] = bsk: softmax-invariant, dropped.
    const float* wsv = (const float*)d_in[13];
    const float* bsv = (const float*)d_in[14];
    const float* wf  = (const float*)d_in[15];
    const float* bf  = (const float*)d_in[16];

    float* out = (float*)d_out;
    float* fin = out + (size_t)BSZ * LSEQ * DM;

    float* scratch = nullptr;
    cudaGetSymbolAddress((void**)&scratch, g_scratch);
    float* qh  = scratch;
    float* kh  = qh + (size_t)BSZ * LSEQ * DM;
    float* vh  = kh + (size_t)BSZ * LSEQ * DM;
    float* ctx = vh + (size_t)BSZ * LSEQ * DM;
    float* ktr = ctx + (size_t)BSZ * LSEQ * DM;
    float* sc0 = ktr + (size_t)BSZ * LSEQ * DM;

    detect_mask_kernel<<<1, 256>>>((const unsigned char*)kmaskp, BSZ * LSEQ);

    qkv_gemm<<<dim3(2, 32, 3), 256>>>(query, key, value,
                                      wq, wk, wv, bq, bk, bv,
                                      qh, kh, vh);

    transpose_k<<<dim3(16, 8, 8), dim3(32, 8)>>>(kh, ktr);

    cudaFuncSetAttribute(attn_kernel, cudaFuncAttributeMaxDynamicSharedMemorySize, SMEM_BYTES);
    attn_kernel<<<BSZ * (LSEQ / TQ), NTHREADS, SMEM_BYTES>>>(
        qh, ktr, vh, structure, kmaskp, wsk, wsv, bsv, ctx, sc0);

    normalize_rows<<<BSZ * LSEQ, 256>>>(sc0, fin);
    gemm128<<<dim3(2, 32), 256>>>(ctx, wf, bf, out, 1.0f);
}